// round 14
// baseline (speedup 1.0000x reference)
#include <cuda_runtime.h>
#include <math.h>

#define BH 16
#define T 384
#define S 384
#define D 64
#define OUT_ELEMS (BH*T*D)   // 393216

// Scratch: Et = exp(2*qp), Es = exp(2*kp), e-major f32: [bh][e][t] / [bh][e][s]
__device__ float4 g_EtT4[BH*D*T/4];
__device__ float4 g_EsT4[BH*D*S/4];

__device__ __forceinline__ float rcpf(float x) {
    float r; asm("rcp.approx.ftz.f32 %0, %1;" : "=f"(r) : "f"(x)); return r;
}

// ---------------------------------------------------------------------------
// Phase 1: EtT[bh][e][t] = exp( 2 * sum_d X[bh][t][d] * W[e][d] )
// grid (16 bh, 6 chunks of 64, 2 which), 256 threads
// ---------------------------------------------------------------------------
__global__ __launch_bounds__(256) void proj_kernel(
    const float* __restrict__ query, const float* __restrict__ key,
    const float* __restrict__ Wq, const float* __restrict__ Wk)
{
    __shared__ float Xs[64][65];
    __shared__ float Ws[64][65];
    int bh = blockIdx.x, chunk = blockIdx.y, which = blockIdx.z;
    const float* X = which ? key : query;
    const float* W = which ? Wk : Wq;
    float* outT = which ? (float*)g_EsT4 : (float*)g_EtT4;
    int tid = threadIdx.x;

    for (int i = tid; i < 64*64; i += 256) {
        int r = i >> 6, c = i & 63;
        Xs[r][c] = X[((size_t)bh*T + (size_t)chunk*64 + r)*D + c];
        Ws[r][c] = W[i];
    }
    __syncthreads();

    int t  = tid & 63;
    int e0 = (tid >> 6) * 16;
    float acc[16];
    #pragma unroll
    for (int k = 0; k < 16; k++) acc[k] = 0.f;

    #pragma unroll 4
    for (int d = 0; d < 64; d++) {
        float xv = Xs[t][d];
        #pragma unroll
        for (int k = 0; k < 16; k++)
            acc[k] = fmaf(xv, Ws[e0+k][d], acc[k]);
    }
    #pragma unroll
    for (int k = 0; k < 16; k++) {
        float p;
        float xe = acc[k] * 2.885390081777927f;  // 2*log2(e)
        asm("ex2.approx.ftz.f32 %0, %1;" : "=f"(p) : "f"(xe));
        outT[((size_t)bh*D + e0 + k)*T + (size_t)chunk*64 + t] = p;
    }
}

// ---------------------------------------------------------------------------
// Phase 2: fused score + softmax + attn@value.
// score* = sum_e (-2 vw_e)/(Et*Es+1)  (constant cancels in softmax).
// e-terms combined in PAIRS over a common denominator:
//   w1/d1 + w2/d2 = (w1*d2 + w2*d1) / (d1*d2)
// -> per element per 2 e-steps: 5 fma-pipe ops + 1 rcp (was 6 + 1 in R12).
// grid (48, 16), 128 threads. CTA: 8 t x 384 s; thread tile 4t x 6s.
// ---------------------------------------------------------------------------
__global__ __launch_bounds__(128) void attn_kernel(
    const float* __restrict__ value, const float* __restrict__ v_w,
    float* __restrict__ out, float* __restrict__ attn)
{
    __shared__ __align__(16) float sh_Es[16*384];  // 24KB chunk; aliased as scores[8][384]
    __shared__ float sh_Et[64][8];                 // [e][t-row]
    __shared__ float sh_w[64];                     // -2*vw

    float (*scores)[384] = (float(*)[384])sh_Es;

    int bh  = blockIdx.y;
    int t0  = blockIdx.x * 8;
    int tid = threadIdx.x;

    // stage Et tile [64 e][8 t] + weights
    const float* Etbase = (const float*)g_EtT4 + (size_t)bh*D*T;
    for (int i = tid; i < 64*8; i += 128) {
        int e = i >> 3, tl = i & 7;
        sh_Et[e][tl] = Etbase[(size_t)e*T + t0 + tl];
    }
    if (tid < 64) sh_w[tid] = -2.f * v_w[tid];

    int sx = tid & 63;   // s-pair lane (0..63); pairs sx+64p, p=0..2
    int tg = tid >> 6;   // t half (0..1): rows tg*4 .. tg*4+3

    float acc[4][6];
    #pragma unroll
    for (int k = 0; k < 4; k++)
        #pragma unroll
        for (int j = 0; j < 6; j++) acc[k][j] = 0.f;

    const float4* Esbase4 = g_EsT4 + (size_t)bh*D*S/4;

    for (int c = 0; c < 4; c++) {
        __syncthreads();
        // load Es chunk: 16 e-rows x 384 s (24KB), coalesced float4, 12/thread
        const float4* src = Esbase4 + (size_t)c*16*S/4;
        float4* dst = (float4*)sh_Es;
        #pragma unroll
        for (int i = tid; i < 16*384/4; i += 128) dst[i] = src[i];
        __syncthreads();

        #pragma unroll
        for (int ep = 0; ep < 8; ep++) {            // e-pairs within chunk
            int ec = 2*ep;
            int e  = c*16 + ec;
            float w1 = sh_w[e], w2 = sh_w[e+1];
            float et1[4], et2[4];
            float2 kb1[3], kb2[3];
            #pragma unroll
            for (int k = 0; k < 4; k++) {
                et1[k] = sh_Et[e][tg*4 + k];
                et2[k] = sh_Et[e+1][tg*4 + k];
            }
            #pragma unroll
            for (int p = 0; p < 3; p++) {
                kb1[p] = *(const float2*)&sh_Es[ ec   *384 + 2*(sx + 64*p)];
                kb2[p] = *(const float2*)&sh_Es[(ec+1)*384 + 2*(sx + 64*p)];
            }

            #pragma unroll
            for (int k = 0; k < 4; k++)
                #pragma unroll
                for (int p = 0; p < 3; p++) {
                    // low element of the s-pair
                    float d1l = fmaf(et1[k], kb1[p].x, 1.f);
                    float d2l = fmaf(et2[k], kb2[p].x, 1.f);
                    float nl  = fmaf(w2, d1l, w1*d2l);
                    float Dl  = d1l*d2l;
                    acc[k][2*p]   = fmaf(nl, rcpf(Dl), acc[k][2*p]);
                    // high element
                    float d1h = fmaf(et1[k], kb1[p].y, 1.f);
                    float d2h = fmaf(et2[k], kb2[p].y, 1.f);
                    float nh  = fmaf(w2, d1h, w1*d2h);
                    float Dh  = d1h*d2h;
                    acc[k][2*p+1] = fmaf(nh, rcpf(Dh), acc[k][2*p+1]);
                }
        }
    }
    __syncthreads();

    // dump scores into the (now free) Es buffer, float2 stores
    #pragma unroll
    for (int k = 0; k < 4; k++)
        #pragma unroll
        for (int p = 0; p < 3; p++)
            *(float2*)&scores[tg*4+k][2*(sx + 64*p)] =
                make_float2(acc[k][2*p], acc[k][2*p+1]);
    __syncthreads();

    // softmax: 4 warps, 2 rows each; write attn to global, keep normalized in smem
    int w = tid >> 5, lane = tid & 31;
    for (int r = w; r < 8; r += 4) {
        float vals[12];
        float m = -1e30f;
        #pragma unroll
        for (int i = 0; i < 12; i++) {
            vals[i] = scores[r][lane + 32*i];
            m = fmaxf(m, vals[i]);
        }
        #pragma unroll
        for (int off = 16; off; off >>= 1)
            m = fmaxf(m, __shfl_xor_sync(0xffffffffu, m, off));
        float sum = 0.f;
        #pragma unroll
        for (int i = 0; i < 12; i++) {
            float p;
            float xe = (vals[i] - m) * 1.4426950408889634f;
            asm("ex2.approx.f32 %0, %1;" : "=f"(p) : "f"(xe));
            vals[i] = p;
            sum += p;
        }
        #pragma unroll
        for (int off = 16; off; off >>= 1)
            sum += __shfl_xor_sync(0xffffffffu, sum, off);
        float inv = 1.0f / sum;
        size_t arow = ((size_t)bh*T + t0 + r) * S;
        #pragma unroll
        for (int i = 0; i < 12; i++) {
            float p = vals[i] * inv;
            scores[r][lane + 32*i] = p;
            attn[arow + lane + 32*i] = p;
        }
    }
    __syncthreads();

    // epilogue: out[t0+tl][d] = sum_s attn[tl][s] * value[s][d]
    int dx = sx;             // 0..63, warp-coalesced value loads
    float accv[4] = {0.f, 0.f, 0.f, 0.f};   // rows tg*4 .. tg*4+3
    const float* vp = value + (size_t)bh*S*D + dx;
    #pragma unroll 2
    for (int s = 0; s < 384; s += 4) {
        float v0 = __ldg(vp + (size_t)(s+0)*D);
        float v1 = __ldg(vp + (size_t)(s+1)*D);
        float v2 = __ldg(vp + (size_t)(s+2)*D);
        float v3 = __ldg(vp + (size_t)(s+3)*D);
        #pragma unroll
        for (int k = 0; k < 4; k++) {
            float4 a = *(const float4*)&scores[tg*4+k][s];
            accv[k] = fmaf(a.x, v0, fmaf(a.y, v1, fmaf(a.z, v2, fmaf(a.w, v3, accv[k]))));
        }
    }
    #pragma unroll
    for (int k = 0; k < 4; k++)
        out[((size_t)bh*T + t0 + tg*4 + k)*D + dx] = accv[k];
}

// ---------------------------------------------------------------------------
extern "C" void kernel_launch(void* const* d_in, const int* in_sizes, int n_in,
                              void* d_out, int out_size)
{
    (void)in_sizes; (void)n_in; (void)out_size;
    const float* query = (const float*)d_in[0];
    const float* key   = (const float*)d_in[1];
    const float* value = (const float*)d_in[2];
    const float* Wq    = (const float*)d_in[3];
    const float* Wk    = (const float*)d_in[4];
    const float* vw    = (const float*)d_in[5];
    float* out  = (float*)d_out;
    float* attn = out + OUT_ELEMS;

    proj_kernel<<<dim3(16, 6, 2), 256>>>(query, key, Wq, Wk);
    attn_kernel<<<dim3(48, 16), 128>>>(value, vw, out, attn);
}

// round 15
// speedup vs baseline: 1.6623x; 1.6623x over previous
#include <cuda_runtime.h>
#include <math.h>

#define BH 16
#define T 384
#define S 384
#define D 64
#define OUT_ELEMS (BH*T*D)   // 393216

typedef unsigned long long u64;

// Scratch: Et = exp(2*qp)  [bh][e][t]
//          Esw = exp(2*kp)/w_e  [bh][e][s],  w_e = -2*v_w[e]
__device__ float4 g_EtT4[BH*D*T/4];
__device__ float4 g_EswT4[BH*D*S/4];

__device__ __forceinline__ float rcpf(float x) {
    float r; asm("rcp.approx.ftz.f32 %0, %1;" : "=f"(r) : "f"(x)); return r;
}
__device__ __forceinline__ u64 pk2(float lo, float hi) {
    u64 r; asm("mov.b64 %0, {%1,%2};" : "=l"(r) : "f"(lo), "f"(hi)); return r;
}
__device__ __forceinline__ void upk2(u64 v, float& lo, float& hi) {
    asm("mov.b64 {%0,%1}, %2;" : "=f"(lo), "=f"(hi) : "l"(v));
}
__device__ __forceinline__ u64 fma2(u64 a, u64 b, u64 c) {
    u64 r; asm("fma.rn.f32x2 %0, %1, %2, %3;" : "=l"(r) : "l"(a), "l"(b), "l"(c)); return r;
}

// ---------------------------------------------------------------------------
// Phase 1: Et[bh][e][t] = exp(2*qp);  Esw[bh][e][s] = exp(2*kp) / w_e
// grid (16 bh, 6 chunks of 64, 2 which), 256 threads
// ---------------------------------------------------------------------------
__global__ __launch_bounds__(256) void proj_kernel(
    const float* __restrict__ query, const float* __restrict__ key,
    const float* __restrict__ Wq, const float* __restrict__ Wk,
    const float* __restrict__ v_w)
{
    __shared__ float Xs[64][65];
    __shared__ float Ws[64][65];
    int bh = blockIdx.x, chunk = blockIdx.y, which = blockIdx.z;
    const float* X = which ? key : query;
    const float* W = which ? Wk : Wq;
    float* outT = which ? (float*)g_EswT4 : (float*)g_EtT4;
    int tid = threadIdx.x;

    for (int i = tid; i < 64*64; i += 256) {
        int r = i >> 6, c = i & 63;
        Xs[r][c] = X[((size_t)bh*T + (size_t)chunk*64 + r)*D + c];
        Ws[r][c] = W[i];
    }
    __syncthreads();

    int t  = tid & 63;
    int e0 = (tid >> 6) * 16;
    float acc[16];
    #pragma unroll
    for (int k = 0; k < 16; k++) acc[k] = 0.f;

    #pragma unroll 4
    for (int d = 0; d < 64; d++) {
        float xv = Xs[t][d];
        #pragma unroll
        for (int k = 0; k < 16; k++)
            acc[k] = fmaf(xv, Ws[e0+k][d], acc[k]);
    }
    #pragma unroll
    for (int k = 0; k < 16; k++) {
        float p;
        float xe = acc[k] * 2.885390081777927f;  // 2*log2(e)
        asm("ex2.approx.ftz.f32 %0, %1;" : "=f"(p) : "f"(xe));
        if (which) p = p / (-2.f * v_w[e0 + k]);  // fold 1/w into Es
        outT[((size_t)bh*D + e0 + k)*T + (size_t)chunk*64 + t] = p;
    }
}

// ---------------------------------------------------------------------------
// Phase 2: fused score + softmax + attn@value.
// score* = sum_e 1/(Et*Esw + invw),  invw = 1/w_e  (constant cancels in softmax)
// Per s-pair: 1 packed fma2 (d') + 1 FMUL (prod) + 1 rcp + 2 FFMA (acc)
//   -> fma pipe 8 cyc/pair, MUFU 8 cyc/pair: balanced floors ~16.3us each.
// grid (48, 16), 128 threads. CTA: 8 t x 384 s; thread tile 4t x 6s.
// ---------------------------------------------------------------------------
__global__ __launch_bounds__(128) void attn_kernel(
    const float* __restrict__ value, const float* __restrict__ v_w,
    float* __restrict__ out, float* __restrict__ attn)
{
    __shared__ __align__(16) float sh_Es[16*384];  // 24KB chunk; aliased as scores[8][384]
    __shared__ __align__(8) u64 sh_Et2[64][8];     // (Et,Et) duplicated pairs
    __shared__ __align__(8) u64 sh_invw2[64];      // (1/w, 1/w)

    float (*scores)[384] = (float(*)[384])sh_Es;

    int bh  = blockIdx.y;
    int t0  = blockIdx.x * 8;
    int tid = threadIdx.x;

    // stage Et tile [64 e][8 t] duplicated + invw duplicated
    const float* Etbase = (const float*)g_EtT4 + (size_t)bh*D*T;
    for (int i = tid; i < 64*8; i += 128) {
        int e = i >> 3, tl = i & 7;
        float a = Etbase[(size_t)e*T + t0 + tl];
        sh_Et2[e][tl] = pk2(a, a);
    }
    if (tid < 64) {
        float iw = 1.0f / (-2.f * v_w[tid]);
        sh_invw2[tid] = pk2(iw, iw);
    }

    int sx = tid & 63;   // s-pair lane (0..63); pairs sx+64p, p=0..2
    int tg = tid >> 6;   // t half (0..1): rows tg*4 .. tg*4+3

    float acc[4][6];
    #pragma unroll
    for (int k = 0; k < 4; k++)
        #pragma unroll
        for (int j = 0; j < 6; j++) acc[k][j] = 0.f;

    const float4* Esbase4 = g_EswT4 + (size_t)bh*D*S/4;

    for (int c = 0; c < 4; c++) {
        __syncthreads();
        // load Esw chunk: 16 e-rows x 384 s (24KB), coalesced float4, 12/thread
        const float4* src = Esbase4 + (size_t)c*16*S/4;
        float4* dst = (float4*)sh_Es;
        #pragma unroll
        for (int i = tid; i < 16*384/4; i += 128) dst[i] = src[i];
        __syncthreads();

        #pragma unroll
        for (int ec = 0; ec < 16; ec++) {
            int e = c*16 + ec;
            u64 invw2 = sh_invw2[e];
            u64 et2[4], kb2[3];
            #pragma unroll
            for (int k = 0; k < 4; k++) et2[k] = sh_Et2[e][tg*4 + k];
            const u64* krow = (const u64*)&sh_Es[ec*384];
            #pragma unroll
            for (int p = 0; p < 3; p++) kb2[p] = krow[sx + 64*p];

            #pragma unroll
            for (int k = 0; k < 4; k++)
                #pragma unroll
                for (int p = 0; p < 3; p++) {
                    u64 d2 = fma2(et2[k], kb2[p], invw2);  // (d'_l, d'_h)
                    float dl, dh;
                    upk2(d2, dl, dh);
                    float inv = rcpf(dl * dh);             // 1/(d'_l * d'_h)
                    acc[k][2*p]   = fmaf(inv, dh, acc[k][2*p]);   // 1/d'_l
                    acc[k][2*p+1] = fmaf(inv, dl, acc[k][2*p+1]); // 1/d'_h
                }
        }
    }
    __syncthreads();

    // dump scores into the (now free) Es buffer, float2 stores
    #pragma unroll
    for (int k = 0; k < 4; k++)
        #pragma unroll
        for (int p = 0; p < 3; p++)
            *(float2*)&scores[tg*4+k][2*(sx + 64*p)] =
                make_float2(acc[k][2*p], acc[k][2*p+1]);
    __syncthreads();

    // softmax: 4 warps, 2 rows each; write attn to global, keep normalized in smem
    int w = tid >> 5, lane = tid & 31;
    for (int r = w; r < 8; r += 4) {
        float vals[12];
        float m = -1e30f;
        #pragma unroll
        for (int i = 0; i < 12; i++) {
            vals[i] = scores[r][lane + 32*i];
            m = fmaxf(m, vals[i]);
        }
        #pragma unroll
        for (int off = 16; off; off >>= 1)
            m = fmaxf(m, __shfl_xor_sync(0xffffffffu, m, off));
        float sum = 0.f;
        #pragma unroll
        for (int i = 0; i < 12; i++) {
            float p;
            float xe = (vals[i] - m) * 1.4426950408889634f;
            asm("ex2.approx.f32 %0, %1;" : "=f"(p) : "f"(xe));
            vals[i] = p;
            sum += p;
        }
        #pragma unroll
        for (int off = 16; off; off >>= 1)
            sum += __shfl_xor_sync(0xffffffffu, sum, off);
        float inv = 1.0f / sum;
        size_t arow = ((size_t)bh*T + t0 + r) * S;
        #pragma unroll
        for (int i = 0; i < 12; i++) {
            float p = vals[i] * inv;
            scores[r][lane + 32*i] = p;
            attn[arow + lane + 32*i] = p;
        }
    }
    __syncthreads();

    // epilogue: out[t0+tl][d] = sum_s attn[tl][s] * value[s][d]
    int dx = sx;             // 0..63, warp-coalesced value loads
    float accv[4] = {0.f, 0.f, 0.f, 0.f};   // rows tg*4 .. tg*4+3
    const float* vp = value + (size_t)bh*S*D + dx;
    #pragma unroll 2
    for (int s = 0; s < 384; s += 4) {
        float v0 = __ldg(vp + (size_t)(s+0)*D);
        float v1 = __ldg(vp + (size_t)(s+1)*D);
        float v2 = __ldg(vp + (size_t)(s+2)*D);
        float v3 = __ldg(vp + (size_t)(s+3)*D);
        #pragma unroll
        for (int k = 0; k < 4; k++) {
            float4 a = *(const float4*)&scores[tg*4+k][s];
            accv[k] = fmaf(a.x, v0, fmaf(a.y, v1, fmaf(a.z, v2, fmaf(a.w, v3, accv[k]))));
        }
    }
    #pragma unroll
    for (int k = 0; k < 4; k++)
        out[((size_t)bh*T + t0 + tg*4 + k)*D + dx] = accv[k];
}

// ---------------------------------------------------------------------------
extern "C" void kernel_launch(void* const* d_in, const int* in_sizes, int n_in,
                              void* d_out, int out_size)
{
    (void)in_sizes; (void)n_in; (void)out_size;
    const float* query = (const float*)d_in[0];
    const float* key   = (const float*)d_in[1];
    const float* value = (const float*)d_in[2];
    const float* Wq    = (const float*)d_in[3];
    const float* Wk    = (const float*)d_in[4];
    const float* vw    = (const float*)d_in[5];
    float* out  = (float*)d_out;
    float* attn = out + OUT_ELEMS;

    proj_kernel<<<dim3(16, 6, 2), 256>>>(query, key, Wq, Wk, vw);
    attn_kernel<<<dim3(48, 16), 128>>>(value, vw, out, attn);
}